// round 2
// baseline (speedup 1.0000x reference)
#include <cuda_runtime.h>

#define NB 16
#define NC 256
#define NPIX 1024
#define NHEADS 4
#define DHEAD 64
#define NG 8
#define CPG 32

// ---- scratch (device globals, no allocation) ----
__device__ float g_h[NB * NC * NPIX];        // groupnorm output  [B][C][N]
__device__ float g_qkv[NB * 3 * NC * NPIX];  // qkv               [B][3*C][N]
__device__ float g_ao[NB * NC * NPIX];       // attention output  [B][C][N]

// ============================================================
// GroupNorm: one block per (b, g). Two passes (data stays in L2).
// ============================================================
__global__ void groupnorm_kernel(const float* __restrict__ x,
                                 const float* __restrict__ gw,
                                 const float* __restrict__ gb) {
    const int GROUP_ELEMS = CPG * NPIX;  // 32768
    int b = blockIdx.x >> 3;
    int g = blockIdx.x & 7;
    size_t base = ((size_t)b * NC + (size_t)g * CPG) * NPIX;
    const float4* xp = reinterpret_cast<const float4*>(x + base);
    int tid = threadIdx.x;

    float s = 0.f, ss = 0.f;
    for (int i = tid; i < GROUP_ELEMS / 4; i += 256) {
        float4 v = xp[i];
        s  += (v.x + v.y) + (v.z + v.w);
        ss += (v.x * v.x + v.y * v.y) + (v.z * v.z + v.w * v.w);
    }
    __shared__ float rs[8], rss[8];
    #pragma unroll
    for (int o = 16; o > 0; o >>= 1) {
        s  += __shfl_xor_sync(0xffffffffu, s, o);
        ss += __shfl_xor_sync(0xffffffffu, ss, o);
    }
    if ((tid & 31) == 0) { rs[tid >> 5] = s; rss[tid >> 5] = ss; }
    __syncthreads();
    __shared__ float smu, sinv;
    if (tid == 0) {
        float ts = 0.f, tss = 0.f;
        #pragma unroll
        for (int i = 0; i < 8; i++) { ts += rs[i]; tss += rss[i]; }
        float mu = ts / (float)GROUP_ELEMS;
        float var = tss / (float)GROUP_ELEMS - mu * mu;
        smu = mu;
        sinv = rsqrtf(var + 1e-5f);
    }
    __syncthreads();
    float mu = smu, inv = sinv;

    float4* hp = reinterpret_cast<float4*>(g_h + base);
    for (int i = tid; i < GROUP_ELEMS / 4; i += 256) {
        int c = g * CPG + ((i * 4) >> 10);  // NPIX = 1024
        float wc = gw[c], bc = gb[c];
        float4 v = xp[i];
        v.x = (v.x - mu) * inv * wc + bc;
        v.y = (v.y - mu) * inv * wc + bc;
        v.z = (v.z - mu) * inv * wc + bc;
        v.w = (v.w - mu) * inv * wc + bc;
        hp[i] = v;
    }
}

// ============================================================
// Tiled SGEMM: OUT[b][o][n] = sum_c W[o][c]*IN[b][c][n] + bias[o] (+ RES)
// 64x64 tile, BK=16, 256 threads, 4x4 register micro-tile.
// grid = (N/64, O/64, B)
// ============================================================
__global__ __launch_bounds__(256)
void gemm_kernel(const float* __restrict__ W,
                 const float* __restrict__ bias,
                 const float* __restrict__ IN,
                 const float* __restrict__ RES,  // may be null
                 float* __restrict__ OUT,
                 int O, int K, int N) {
    __shared__ float Ws[16][64];  // [k][o]
    __shared__ float Is[16][64];  // [k][n]

    int tid = threadIdx.x;
    int tx = tid & 15, ty = tid >> 4;
    int n0 = blockIdx.x * 64;
    int o0 = blockIdx.y * 64;
    size_t boff = (size_t)blockIdx.z * (size_t)K * N;
    size_t ooff = (size_t)blockIdx.z * (size_t)O * N;

    float acc[4][4] = {};
    int wrow = tid >> 2, wc4 = tid & 3;   // W tile loader
    int irow = tid >> 4, in4 = tid & 15;  // IN tile loader

    for (int k0 = 0; k0 < K; k0 += 16) {
        float4 w4 = *reinterpret_cast<const float4*>(
            W + (size_t)(o0 + wrow) * K + k0 + wc4 * 4);
        float4 i4 = *reinterpret_cast<const float4*>(
            IN + boff + (size_t)(k0 + irow) * N + n0 + in4 * 4);
        Ws[wc4 * 4 + 0][wrow] = w4.x;
        Ws[wc4 * 4 + 1][wrow] = w4.y;
        Ws[wc4 * 4 + 2][wrow] = w4.z;
        Ws[wc4 * 4 + 3][wrow] = w4.w;
        *reinterpret_cast<float4*>(&Is[irow][in4 * 4]) = i4;
        __syncthreads();
        #pragma unroll
        for (int kk = 0; kk < 16; kk++) {
            float4 a = *reinterpret_cast<float4*>(&Ws[kk][ty * 4]);
            float4 bb = *reinterpret_cast<float4*>(&Is[kk][tx * 4]);
            float av[4] = {a.x, a.y, a.z, a.w};
            float bv[4] = {bb.x, bb.y, bb.z, bb.w};
            #pragma unroll
            for (int i = 0; i < 4; i++)
                #pragma unroll
                for (int j = 0; j < 4; j++)
                    acc[i][j] = fmaf(av[i], bv[j], acc[i][j]);
        }
        __syncthreads();
    }

    #pragma unroll
    for (int i = 0; i < 4; i++) {
        int o = o0 + ty * 4 + i;
        float bi = bias[o];
        size_t row = ooff + (size_t)o * N + n0 + tx * 4;
        float4 r = make_float4(acc[i][0] + bi, acc[i][1] + bi,
                               acc[i][2] + bi, acc[i][3] + bi);
        if (RES) {
            float4 rv = *reinterpret_cast<const float4*>(RES + row);
            r.x += rv.x; r.y += rv.y; r.z += rv.z; r.w += rv.w;
        }
        *reinterpret_cast<float4*>(OUT + row) = r;
    }
}

// ============================================================
// Flash attention, fp32. grid = (N/64 q-tiles, B*NHEADS).
// smem: Qs[64c][64q] + KPs[64][64] (K tile, reused for P and O-staging)
//       + Vs[64d][64m] with XOR-rotation swizzle (conflict-free PV reads).
// Exactly 48 KB static shared.
// ============================================================
__global__ __launch_bounds__(256)
void attn_kernel() {
    __shared__ float Qs[64 * 64];
    __shared__ float KPs[64 * 64];
    __shared__ float Vs[64 * 64];

    int tid = threadIdx.x;
    int tx = tid & 15, ty = tid >> 4;
    int q0 = blockIdx.x * 64;
    int bh = blockIdx.y;
    int b = bh >> 2, h = bh & 3;
    const float scale = 0.125f;  // 64^-0.5

    size_t qbase = (((size_t)b * 3 + 0) * NHEADS + h) * (size_t)(DHEAD * NPIX);
    size_t kbase = (((size_t)b * 3 + 1) * NHEADS + h) * (size_t)(DHEAD * NPIX);
    size_t vbase = (((size_t)b * 3 + 2) * NHEADS + h) * (size_t)(DHEAD * NPIX);

    // load Q tile (pre-scaled): Qs[c][q]
    #pragma unroll
    for (int it = 0; it < 4; it++) {
        int idx = it * 256 + tid;
        int c = idx >> 4, q4 = (idx & 15) * 4;
        float4 v = *reinterpret_cast<const float4*>(
            g_qkv + qbase + (size_t)c * NPIX + q0 + q4);
        v.x *= scale; v.y *= scale; v.z *= scale; v.w *= scale;
        *reinterpret_cast<float4*>(&Qs[c * 64 + q4]) = v;
    }

    float o[4][4] = {};
    float mi[4] = {-1e30f, -1e30f, -1e30f, -1e30f};
    float li[4] = {};

    for (int m0 = 0; m0 < NPIX; m0 += 64) {
        // load K tile -> KPs[c][m]; V tile -> Vs[c][(m + c) & 63] (swizzled)
        #pragma unroll
        for (int it = 0; it < 4; it++) {
            int idx = it * 256 + tid;
            int c = idx >> 4, m4 = (idx & 15) * 4;
            float4 kv = *reinterpret_cast<const float4*>(
                g_qkv + kbase + (size_t)c * NPIX + m0 + m4);
            *reinterpret_cast<float4*>(&KPs[c * 64 + m4]) = kv;
            float4 vv = *reinterpret_cast<const float4*>(
                g_qkv + vbase + (size_t)c * NPIX + m0 + m4);
            Vs[c * 64 + ((m4 + 0 + c) & 63)] = vv.x;
            Vs[c * 64 + ((m4 + 1 + c) & 63)] = vv.y;
            Vs[c * 64 + ((m4 + 2 + c) & 63)] = vv.z;
            Vs[c * 64 + ((m4 + 3 + c) & 63)] = vv.w;
        }
        __syncthreads();

        // S[q][m] = sum_c Qs[c][q] * K[c][m], q = ty*4+i, m = tx*4+j
        float s[4][4] = {};
        #pragma unroll 16
        for (int cc = 0; cc < 64; cc++) {
            float4 a = *reinterpret_cast<float4*>(&Qs[cc * 64 + ty * 4]);
            float4 bb = *reinterpret_cast<float4*>(&KPs[cc * 64 + tx * 4]);
            float av[4] = {a.x, a.y, a.z, a.w};
            float bv[4] = {bb.x, bb.y, bb.z, bb.w};
            #pragma unroll
            for (int i = 0; i < 4; i++)
                #pragma unroll
                for (int j = 0; j < 4; j++)
                    s[i][j] = fmaf(av[i], bv[j], s[i][j]);
        }

        // online softmax (row reduce across 16 tx lanes)
        #pragma unroll
        for (int i = 0; i < 4; i++) {
            float mx = fmaxf(fmaxf(s[i][0], s[i][1]), fmaxf(s[i][2], s[i][3]));
            #pragma unroll
            for (int off = 8; off > 0; off >>= 1)
                mx = fmaxf(mx, __shfl_xor_sync(0xffffffffu, mx, off));
            float mnew = fmaxf(mi[i], mx);
            float alpha = __expf(mi[i] - mnew);
            float ps = 0.f;
            #pragma unroll
            for (int j = 0; j < 4; j++) {
                s[i][j] = __expf(s[i][j] - mnew);
                ps += s[i][j];
            }
            #pragma unroll
            for (int off = 8; off > 0; off >>= 1)
                ps += __shfl_xor_sync(0xffffffffu, ps, off);
            li[i] = li[i] * alpha + ps;
            mi[i] = mnew;
            #pragma unroll
            for (int j = 0; j < 4; j++) o[i][j] *= alpha;
        }

        __syncthreads();  // done reading KPs as K
        // write P into KPs[q][m]
        #pragma unroll
        for (int i = 0; i < 4; i++)
            *reinterpret_cast<float4*>(&KPs[(ty * 4 + i) * 64 + tx * 4]) =
                make_float4(s[i][0], s[i][1], s[i][2], s[i][3]);
        __syncthreads();

        // O[q][d] += sum_m P[q][m] * V[d][m],  d = tx + 16*j (conflict-free)
        #pragma unroll 8
        for (int mm = 0; mm < 64; mm++) {
            float pf[4], vf[4];
            #pragma unroll
            for (int i = 0; i < 4; i++) pf[i] = KPs[(ty * 4 + i) * 64 + mm];
            #pragma unroll
            for (int j = 0; j < 4; j++) {
                int d = tx + 16 * j;
                vf[j] = Vs[d * 64 + ((mm + d) & 63)];
            }
            #pragma unroll
            for (int i = 0; i < 4; i++)
                #pragma unroll
                for (int j = 0; j < 4; j++)
                    o[i][j] = fmaf(pf[i], vf[j], o[i][j]);
        }
        __syncthreads();  // before next tile overwrites KPs/Vs
    }

    // normalize, stage transposed into KPs[d][q], then coalesced store
    #pragma unroll
    for (int i = 0; i < 4; i++) {
        float invl = 1.f / li[i];
        #pragma unroll
        for (int j = 0; j < 4; j++) {
            int d = tx + 16 * j;
            KPs[d * 64 + ty * 4 + i] = o[i][j] * invl;
        }
    }
    __syncthreads();
    size_t obase = ((size_t)b * NC + (size_t)h * DHEAD) * NPIX;
    #pragma unroll
    for (int it = 0; it < 4; it++) {
        int idx = it * 256 + tid;
        int d = idx >> 4, q4 = (idx & 15) * 4;
        *reinterpret_cast<float4*>(g_ao + obase + (size_t)d * NPIX + q0 + q4) =
            *reinterpret_cast<float4*>(&KPs[d * 64 + q4]);
    }
}

// ============================================================
extern "C" void kernel_launch(void* const* d_in, const int* in_sizes, int n_in,
                              void* d_out, int out_size) {
    const float* x      = (const float*)d_in[0];
    const float* norm_w = (const float*)d_in[1];
    const float* norm_b = (const float*)d_in[2];
    const float* qkv_w  = (const float*)d_in[3];
    const float* qkv_b  = (const float*)d_in[4];
    const float* proj_w = (const float*)d_in[5];
    const float* proj_b = (const float*)d_in[6];
    float* out = (float*)d_out;

    void *ph = nullptr, *pqkv = nullptr, *pao = nullptr;
    cudaGetSymbolAddress(&ph, g_h);
    cudaGetSymbolAddress(&pqkv, g_qkv);
    cudaGetSymbolAddress(&pao, g_ao);

    // 1) GroupNorm
    groupnorm_kernel<<<NB * NG, 256>>>(x, norm_w, norm_b);

    // 2) QKV GEMM: [768,256] x [256,1024] per batch
    gemm_kernel<<<dim3(NPIX / 64, (3 * NC) / 64, NB), 256>>>(
        qkv_w, qkv_b, (const float*)ph, nullptr, (float*)pqkv,
        3 * NC, NC, NPIX);

    // 3) Attention
    attn_kernel<<<dim3(NPIX / 64, NB * NHEADS), 256>>>();

    // 4) Proj GEMM + bias + residual -> d_out
    gemm_kernel<<<dim3(NPIX / 64, NC / 64, NB), 256>>>(
        proj_w, proj_b, (const float*)pao, x, out,
        NC, NC, NPIX);
}

// round 12
// speedup vs baseline: 2.8936x; 2.8936x over previous
#include <cuda_runtime.h>
#include <cstdint>

#define NB 16
#define NC 256
#define NPIX 1024
#define NHEADS 4
#define NG 8
#define CPG 32

// ---- scratch (device globals, no allocation) ----
__device__ float g_ht[NB * NPIX * NC];       // groupnorm output TRANSPOSED [B][N][C]
__device__ float g_qkv[NB * 3 * NC * NPIX];  // qkv [B][3*C][N]
__device__ float g_aot[NB * NPIX * NC];      // attention output TRANSPOSED [B][N][C]

__device__ __forceinline__ uint32_t f2tf32(float f) {
    uint32_t u; asm("cvt.rna.tf32.f32 %0, %1;" : "=r"(u) : "f"(f)); return u;
}

// D += A(16x8) * B(8x8), tf32 inputs, f32 accum. (PTX ISA 7.0, sm_80+)
__device__ __forceinline__ void mma_tf32(float* d, const uint32_t* a, const uint32_t* b) {
    asm volatile(
        "mma.sync.aligned.m16n8k8.row.col.f32.tf32.tf32.f32 "
        "{%0,%1,%2,%3}, {%4,%5,%6,%7}, {%8,%9}, {%0,%1,%2,%3};\n"
        : "+f"(d[0]), "+f"(d[1]), "+f"(d[2]), "+f"(d[3])
        : "r"(a[0]), "r"(a[1]), "r"(a[2]), "r"(a[3]), "r"(b[0]), "r"(b[1]));
}

// ============================================================
// GroupNorm -> transposed output g_ht[b][n][c]
// ============================================================
__global__ __launch_bounds__(256)
void groupnorm_t(const float* __restrict__ x,
                 const float* __restrict__ gw,
                 const float* __restrict__ gb) {
    const int GROUP_ELEMS = CPG * NPIX;
    int b = blockIdx.x >> 3;
    int g = blockIdx.x & 7;
    size_t base = ((size_t)b * NC + (size_t)g * CPG) * NPIX;
    const float4* xp = reinterpret_cast<const float4*>(x + base);
    int tid = threadIdx.x;

    float s = 0.f, ss = 0.f;
    for (int i = tid; i < GROUP_ELEMS / 4; i += 256) {
        float4 v = xp[i];
        s  += (v.x + v.y) + (v.z + v.w);
        ss += (v.x * v.x + v.y * v.y) + (v.z * v.z + v.w * v.w);
    }
    __shared__ float rs[8], rss[8];
    #pragma unroll
    for (int o = 16; o > 0; o >>= 1) {
        s  += __shfl_xor_sync(0xffffffffu, s, o);
        ss += __shfl_xor_sync(0xffffffffu, ss, o);
    }
    if ((tid & 31) == 0) { rs[tid >> 5] = s; rss[tid >> 5] = ss; }
    __syncthreads();
    __shared__ float smu, sinv;
    if (tid == 0) {
        float ts = 0.f, tss = 0.f;
        #pragma unroll
        for (int i = 0; i < 8; i++) { ts += rs[i]; tss += rss[i]; }
        float mu = ts / (float)GROUP_ELEMS;
        float var = tss / (float)GROUP_ELEMS - mu * mu;
        smu = mu;
        sinv = rsqrtf(var + 1e-5f);
    }
    __syncthreads();
    float mu = smu, inv = sinv;

    // pass2: normalize + 32x32 smem transpose -> g_ht[b][n][c]
    __shared__ __align__(16) float st[32 * 36];
    int c  = tid >> 3, j8 = tid & 7;
    float sc = gw[g * 32 + c] * inv;
    float sh = gb[g * 32 + c] - mu * sc;
    size_t obase = (size_t)b * (NPIX * NC) + g * 32;

    for (int n0 = 0; n0 < NPIX; n0 += 32) {
        float4 v = *reinterpret_cast<const float4*>(x + base + (size_t)c * NPIX + n0 + j8 * 4);
        st[(j8 * 4 + 0) * 36 + c] = v.x * sc + sh;
        st[(j8 * 4 + 1) * 36 + c] = v.y * sc + sh;
        st[(j8 * 4 + 2) * 36 + c] = v.z * sc + sh;
        st[(j8 * 4 + 3) * 36 + c] = v.w * sc + sh;
        __syncthreads();
        int nl = tid >> 3, c4 = tid & 7;
        float4 o = *reinterpret_cast<float4*>(&st[nl * 36 + c4 * 4]);
        *reinterpret_cast<float4*>(g_ht + obase + (size_t)(n0 + nl) * NC + c4 * 4) = o;
        __syncthreads();
    }
}

// ============================================================
// tf32 mma.sync GEMM: OUT[b][o][n] = sum_k W[o][k]*Bm[b][n][k] + bias[o] (+RES)
// Block tile 128(o) x 128(n), K=256 in chunks of 32. 8 warps, warp tile 64x32.
// grid = (1024/128, O/128, B)
// ============================================================
__global__ __launch_bounds__(256)
void gemm_mma(const float* __restrict__ W, const float* __restrict__ bias,
              const float* __restrict__ Bm, const float* __restrict__ RES,
              float* __restrict__ OUT, int Odim) {
    __shared__ __align__(16) uint32_t As[128 * 36];
    __shared__ __align__(16) uint32_t Bs[128 * 36];

    int tid = threadIdx.x, wid = tid >> 5, lane = tid & 31;
    int gid = lane >> 2, tig = lane & 3;
    int n0 = blockIdx.x * 128, o0 = blockIdx.y * 128;
    const float* gA = W + (size_t)o0 * 256;
    const float* gB = Bm + (size_t)blockIdx.z * NPIX * NC + (size_t)n0 * 256;
    int wm = (wid & 1) * 64, wn = (wid >> 1) * 32;

    float acc[4][4][4] = {};

    for (int k0 = 0; k0 < 256; k0 += 32) {
        #pragma unroll
        for (int it = 0; it < 4; it++) {
            int idx = it * 256 + tid;
            int r = idx >> 3, j = (idx & 7) * 4;
            float4 va = *reinterpret_cast<const float4*>(gA + (size_t)r * 256 + k0 + j);
            float4 vb = *reinterpret_cast<const float4*>(gB + (size_t)r * 256 + k0 + j);
            uint4 ua = {f2tf32(va.x), f2tf32(va.y), f2tf32(va.z), f2tf32(va.w)};
            uint4 ub = {f2tf32(vb.x), f2tf32(vb.y), f2tf32(vb.z), f2tf32(vb.w)};
            *reinterpret_cast<uint4*>(&As[r * 36 + j]) = ua;
            *reinterpret_cast<uint4*>(&Bs[r * 36 + j]) = ub;
        }
        __syncthreads();

        #pragma unroll
        for (int ks = 0; ks < 4; ks++) {
            int k = ks * 8;
            uint32_t af[4][4], bf[4][2];
            #pragma unroll
            for (int i = 0; i < 4; i++) {
                const uint32_t* p = &As[(wm + i * 16 + gid) * 36 + k + tig];
                af[i][0] = p[0]; af[i][1] = p[8 * 36];
                af[i][2] = p[4]; af[i][3] = p[8 * 36 + 4];
            }
            #pragma unroll
            for (int j = 0; j < 4; j++) {
                const uint32_t* p = &Bs[(wn + j * 8 + gid) * 36 + k + tig];
                bf[j][0] = p[0]; bf[j][1] = p[4];
            }
            #pragma unroll
            for (int i = 0; i < 4; i++)
                #pragma unroll
                for (int j = 0; j < 4; j++)
                    mma_tf32(acc[i][j], af[i], bf[j]);
        }
        __syncthreads();
    }

    // epilogue: c0,c1 -> (row, 2*tig..+1); c2,c3 -> (row+8, ...)
    size_t bO = (size_t)blockIdx.z * (size_t)Odim * NPIX;
    #pragma unroll
    for (int i = 0; i < 4; i++) {
        int r0 = o0 + wm + i * 16 + gid;
        float bi0 = bias[r0], bi1 = bias[r0 + 8];
        #pragma unroll
        for (int j = 0; j < 4; j++) {
            int col = n0 + wn + j * 8 + 2 * tig;
            size_t a0 = bO + (size_t)r0 * NPIX + col;
            size_t a1 = bO + (size_t)(r0 + 8) * NPIX + col;
            float2 v0 = {acc[i][j][0] + bi0, acc[i][j][1] + bi0};
            float2 v1 = {acc[i][j][2] + bi1, acc[i][j][3] + bi1};
            if (RES) {
                float2 r = *reinterpret_cast<const float2*>(RES + a0);
                v0.x += r.x; v0.y += r.y;
                r = *reinterpret_cast<const float2*>(RES + a1);
                v1.x += r.x; v1.y += r.y;
            }
            *reinterpret_cast<float2*>(OUT + a0) = v0;
            *reinterpret_cast<float2*>(OUT + a1) = v1;
        }
    }
}

// ============================================================
// Flash attention with tf32 mma.sync.
// grid = (N/64 q-tiles, B*NHEADS), 256 threads (8 warps).
// Warp grid 2(row)x4(col): rows->q, cols->m (for S) / d (for O).
// smem: Qt[64][68] ([q][c] tf32), Ks[64][68] ([c][m] tf32),
//       Vs[64][68] ([d][m] tf32), Ss[64][68] (S f32, then P tf32), + row state.
// ============================================================
#define APITCH 68
#define ATILE (64 * APITCH)

__global__ __launch_bounds__(256)
void attn_mma() {
    extern __shared__ __align__(16) float smf[];
    uint32_t* Qt = reinterpret_cast<uint32_t*>(smf);
    uint32_t* Ks = reinterpret_cast<uint32_t*>(smf + ATILE);
    uint32_t* Vs = reinterpret_cast<uint32_t*>(smf + 2 * ATILE);
    float*    Ss = smf + 3 * ATILE;
    float*  mi_s = smf + 4 * ATILE;
    float*  li_s = mi_s + 64;
    float*  al_s = li_s + 64;

    int tid = threadIdx.x, wid = tid >> 5, lane = tid & 31;
    int gid = lane >> 2, tig = lane & 3;
    int q0 = blockIdx.x * 64;
    int b = blockIdx.y >> 2, h = blockIdx.y & 3;
    int wq = (wid & 1) * 32;       // warp row-offset (q)
    int wc = (wid >> 1) * 16;      // warp col-offset (m for S, d for O)

    size_t qb = ((size_t)b * 768 + h * 64) * (size_t)NPIX;
    size_t kb = ((size_t)b * 768 + 256 + h * 64) * (size_t)NPIX;
    size_t vb = ((size_t)b * 768 + 512 + h * 64) * (size_t)NPIX;

    // load Q, transpose to [q][c], scale by d^-1/2 = 0.125, tf32 convert
    #pragma unroll
    for (int it = 0; it < 4; it++) {
        int idx = it * 256 + tid;
        int c = idx >> 4, q4 = (idx & 15) * 4;
        float4 v = *reinterpret_cast<const float4*>(g_qkv + qb + (size_t)c * NPIX + q0 + q4);
        Qt[(q4 + 0) * APITCH + c] = f2tf32(v.x * 0.125f);
        Qt[(q4 + 1) * APITCH + c] = f2tf32(v.y * 0.125f);
        Qt[(q4 + 2) * APITCH + c] = f2tf32(v.z * 0.125f);
        Qt[(q4 + 3) * APITCH + c] = f2tf32(v.w * 0.125f);
    }
    if (tid < 64) { mi_s[tid] = -1e30f; li_s[tid] = 0.f; }

    float oacc[2][2][4] = {};

    for (int m0 = 0; m0 < NPIX; m0 += 64) {
        // load K [c][m] and V [d][m] tiles, tf32 convert (coalesced)
        #pragma unroll
        for (int it = 0; it < 4; it++) {
            int idx = it * 256 + tid;
            int c = idx >> 4, m4 = (idx & 15) * 4;
            float4 kv = *reinterpret_cast<const float4*>(g_qkv + kb + (size_t)c * NPIX + m0 + m4);
            float4 vv = *reinterpret_cast<const float4*>(g_qkv + vb + (size_t)c * NPIX + m0 + m4);
            uint4 uk = {f2tf32(kv.x), f2tf32(kv.y), f2tf32(kv.z), f2tf32(kv.w)};
            uint4 uv = {f2tf32(vv.x), f2tf32(vv.y), f2tf32(vv.z), f2tf32(vv.w)};
            *reinterpret_cast<uint4*>(&Ks[c * APITCH + m4]) = uk;
            *reinterpret_cast<uint4*>(&Vs[c * APITCH + m4]) = uv;
        }
        __syncthreads();

        // S[q][m] = Qt x K  (k = c = 64)
        float sacc[2][2][4] = {};
        #pragma unroll
        for (int k8 = 0; k8 < 8; k8++) {
            int k = k8 * 8;
            uint32_t af[2][4], bf[2][2];
            #pragma unroll
            for (int i = 0; i < 2; i++) {
                const uint32_t* p = &Qt[(wq + i * 16 + gid) * APITCH + k + tig];
                af[i][0] = p[0]; af[i][1] = p[8 * APITCH];
                af[i][2] = p[4]; af[i][3] = p[8 * APITCH + 4];
            }
            #pragma unroll
            for (int j = 0; j < 2; j++) {
                const uint32_t* p = &Ks[(k + tig) * APITCH + wc + j * 8 + gid];
                bf[j][0] = p[0]; bf[j][1] = p[4 * APITCH];
            }
            #pragma unroll
            for (int i = 0; i < 2; i++)
                #pragma unroll
                for (int j = 0; j < 2; j++)
                    mma_tf32(sacc[i][j], af[i], bf[j]);
        }
        // store S tile to smem
        #pragma unroll
        for (int i = 0; i < 2; i++)
            #pragma unroll
            for (int j = 0; j < 2; j++) {
                int r = wq + i * 16 + gid, c = wc + j * 8 + 2 * tig;
                *reinterpret_cast<float2*>(&Ss[r * APITCH + c]) =
                    make_float2(sacc[i][j][0], sacc[i][j][1]);
                *reinterpret_cast<float2*>(&Ss[(r + 8) * APITCH + c]) =
                    make_float2(sacc[i][j][2], sacc[i][j][3]);
            }
        __syncthreads();

        // online softmax: 4 threads per row, 16 cols each
        {
            int r = tid >> 2, l4 = tid & 3;
            float* srow = &Ss[r * APITCH + l4 * 16];
            float4 s0 = *reinterpret_cast<float4*>(srow + 0);
            float4 s1 = *reinterpret_cast<float4*>(srow + 4);
            float4 s2 = *reinterpret_cast<float4*>(srow + 8);
            float4 s3 = *reinterpret_cast<float4*>(srow + 12);
            float mx = fmaxf(fmaxf(fmaxf(s0.x, s0.y), fmaxf(s0.z, s0.w)),
                             fmaxf(fmaxf(s1.x, s1.y), fmaxf(s1.z, s1.w)));
            mx = fmaxf(mx, fmaxf(fmaxf(fmaxf(s2.x, s2.y), fmaxf(s2.z, s2.w)),
                                 fmaxf(fmaxf(s3.x, s3.y), fmaxf(s3.z, s3.w))));
            mx = fmaxf(mx, __shfl_xor_sync(0xffffffffu, mx, 1));
            mx = fmaxf(mx, __shfl_xor_sync(0xffffffffu, mx, 2));
            float mold = mi_s[r];
            float mnew = fmaxf(mold, mx);
            float alpha = __expf(mold - mnew);
            float p[16] = {s0.x, s0.y, s0.z, s0.w, s1.x, s1.y, s1.z, s1.w,
                           s2.x, s2.y, s2.z, s2.w, s3.x, s3.y, s3.z, s3.w};
            float ps = 0.f;
            #pragma unroll
            for (int e = 0; e < 16; e++) { p[e] = __expf(p[e] - mnew); ps += p[e]; }
            ps += __shfl_xor_sync(0xffffffffu, ps, 1);
            ps += __shfl_xor_sync(0xffffffffu, ps, 2);
            uint32_t* prow = reinterpret_cast<uint32_t*>(srow);
            #pragma unroll
            for (int e4 = 0; e4 < 4; e4++) {
                uint4 up = {f2tf32(p[e4 * 4 + 0]), f2tf32(p[e4 * 4 + 1]),
                            f2tf32(p[e4 * 4 + 2]), f2tf32(p[e4 * 4 + 3])};
                *reinterpret_cast<uint4*>(prow + e4 * 4) = up;
            }
            if (l4 == 0) {
                mi_s[r] = mnew;
                li_s[r] = li_s[r] * alpha + ps;
                al_s[r] = alpha;
            }
        }
        __syncthreads();

        // rescale O by alpha, then O += P x V^T  (k = m = 64)
        #pragma unroll
        for (int i = 0; i < 2; i++) {
            float a_lo = al_s[wq + i * 16 + gid];
            float a_hi = al_s[wq + i * 16 + gid + 8];
            #pragma unroll
            for (int j = 0; j < 2; j++) {
                oacc[i][j][0] *= a_lo; oacc[i][j][1] *= a_lo;
                oacc[i][j][2] *= a_hi; oacc[i][j][3] *= a_hi;
            }
        }
        const uint32_t* Ps = reinterpret_cast<const uint32_t*>(Ss);
        #pragma unroll
        for (int k8 = 0; k8 < 8; k8++) {
            int k = k8 * 8;
            uint32_t af[2][4], bf[2][2];
            #pragma unroll
            for (int i = 0; i < 2; i++) {
                const uint32_t* p = &Ps[(wq + i * 16 + gid) * APITCH + k + tig];
                af[i][0] = p[0]; af[i][1] = p[8 * APITCH];
                af[i][2] = p[4]; af[i][3] = p[8 * APITCH + 4];
            }
            #pragma unroll
            for (int j = 0; j < 2; j++) {
                const uint32_t* p = &Vs[(wc + j * 8 + gid) * APITCH + k + tig];
                bf[j][0] = p[0]; bf[j][1] = p[4];
            }
            #pragma unroll
            for (int i = 0; i < 2; i++)
                #pragma unroll
                for (int j = 0; j < 2; j++)
                    mma_tf32(oacc[i][j], af[i], bf[j]);
        }
        __syncthreads();
    }

    // normalize and write g_aot[b][n=q][c = h*64 + d]
    #pragma unroll
    for (int i = 0; i < 2; i++) {
        int q_lo = wq + i * 16 + gid, q_hi = q_lo + 8;
        float il0 = 1.f / li_s[q_lo];
        float il1 = 1.f / li_s[q_hi];
        #pragma unroll
        for (int j = 0; j < 2; j++) {
            int d = h * 64 + wc + j * 8 + 2 * tig;
            size_t a0 = ((size_t)b * NPIX + q0 + q_lo) * NC + d;
            size_t a1 = ((size_t)b * NPIX + q0 + q_hi) * NC + d;
            *reinterpret_cast<float2*>(g_aot + a0) =
                make_float2(oacc[i][j][0] * il0, oacc[i][j][1] * il0);
            *reinterpret_cast<float2*>(g_aot + a1) =
                make_float2(oacc[i][j][2] * il1, oacc[i][j][3] * il1);
        }
    }
}

#define ATTN_SMEM ((4 * ATILE + 3 * 64) * 4)

// ============================================================
extern "C" void kernel_launch(void* const* d_in, const int* in_sizes, int n_in,
                              void* d_out, int out_size) {
    const float* x      = (const float*)d_in[0];
    const float* norm_w = (const float*)d_in[1];
    const float* norm_b = (const float*)d_in[2];
    const float* qkv_w  = (const float*)d_in[3];
    const float* qkv_b  = (const float*)d_in[4];
    const float* proj_w = (const float*)d_in[5];
    const float* proj_b = (const float*)d_in[6];
    float* out = (float*)d_out;

    void *pht = nullptr, *pqkv = nullptr, *paot = nullptr;
    cudaGetSymbolAddress(&pht, g_ht);
    cudaGetSymbolAddress(&pqkv, g_qkv);
    cudaGetSymbolAddress(&paot, g_aot);

    cudaFuncSetAttribute(attn_mma, cudaFuncAttributeMaxDynamicSharedMemorySize, ATTN_SMEM);

    // 1) GroupNorm -> g_ht [b][n][c]
    groupnorm_t<<<NB * NG, 256>>>(x, norm_w, norm_b);

    // 2) QKV GEMM (tf32 mma.sync): W[768,256] x ht -> g_qkv [b][o][n]
    gemm_mma<<<dim3(NPIX / 128, 768 / 128, NB), 256>>>(
        qkv_w, qkv_b, (const float*)pht, nullptr, (float*)pqkv, 768);

    // 3) Attention (tf32 mma.sync flash) -> g_aot [b][n][c]
    attn_mma<<<dim3(NPIX / 64, NB * NHEADS), 256, ATTN_SMEM>>>();

    // 4) Proj GEMM (tf32 mma.sync) + bias + residual -> d_out
    gemm_mma<<<dim3(NPIX / 128, NC / 128, NB), 256>>>(
        proj_w, proj_b, (const float*)paot, x, out, NC);
}